// round 16
// baseline (speedup 1.0000x reference)
#include <cuda_runtime.h>
#include <cuda_bf16.h>
#include <math.h>
#include <stdint.h>

#define B_SZ 2
#define SEQ 4162
#define DM 1024
#define DI 2048
#define DSTATE 64
#define HD 128
#define NH 16
#define NL 4
#define CONV_DIM 2176
#define DIP 4240
#define MR (B_SZ*SEQ)          // 8324 rows
#define NPIX (B_SZ*4096)       // 8192
#define YHAT_ELEMS (NPIX*3)    // 24576
#define LCH 256                // scan chunk length
#define TCH 17                 // ceil(SEQ/LCH)

// ---------------- scratch (static device allocations; no cudaMalloc) -------
__device__ float g_x[(size_t)MR*DM];        // residual stream
__device__ float g_zx[(size_t)MR*DIP];      // in_proj output
__device__ float g_xBC[(size_t)MR*CONV_DIM];// conv+silu output
__device__ float g_y[(size_t)MR*DI];        // scan output
__device__ float g_dt[MR*NH];
__device__ float g_dA[MR*NH];
__device__ float g_part[NPIX];
// chunked-scan state buffers
__device__ float g_S[(size_t)B_SZ*NH*TCH*HD*DSTATE];
__device__ float g_Hb[(size_t)B_SZ*NH*TCH*HD*DSTATE];
__device__ float g_P[B_SZ*NH*TCH];
// bf16 hi/lo split buffers
__device__ __nv_bfloat16 g_lnh[(size_t)MR*DM];
__device__ __nv_bfloat16 g_lnl[(size_t)MR*DM];
__device__ __nv_bfloat16 g_yh[(size_t)MR*DI];
__device__ __nv_bfloat16 g_yl[(size_t)MR*DI];
__device__ __nv_bfloat16 g_w1h[(size_t)NL*DIP*DM];
__device__ __nv_bfloat16 g_w1l[(size_t)NL*DIP*DM];
__device__ __nv_bfloat16 g_w2h[(size_t)NL*DM*DI];
__device__ __nv_bfloat16 g_w2l[(size_t)NL*DM*DI];

// ---------------- helpers ---------------------------------------------------
__device__ __forceinline__ float siluf(float x) { return x / (1.f + expf(-x)); }

__device__ __forceinline__ float blockSumN(float v, float* red, int nwarp) {
    int lane = threadIdx.x & 31, wid = threadIdx.x >> 5;
#pragma unroll
    for (int o = 16; o; o >>= 1) v += __shfl_xor_sync(0xffffffffu, v, o);
    if (lane == 0) red[wid] = v;
    __syncthreads();
    float r = 0.f;
    for (int i = 0; i < nwarp; i++) r += red[i];
    __syncthreads();
    return r;
}

__device__ __forceinline__ void bf16split2(float x, float y, uint32_t& hi, uint32_t& lo) {
    __nv_bfloat162 h = __floats2bfloat162_rn(x, y);
    uint32_t hw = *reinterpret_cast<uint32_t*>(&h);
    float hx = __uint_as_float(hw << 16);
    float hy = __uint_as_float(hw & 0xffff0000u);
    __nv_bfloat162 l = __floats2bfloat162_rn(x - hx, y - hy);
    hi = hw;
    lo = *reinterpret_cast<uint32_t*>(&l);
}

__device__ __forceinline__ uint32_t smem_u32(const void* p) {
    uint32_t a;
    asm("{ .reg .u64 t; cvta.to.shared.u64 t, %1; cvt.u32.u64 %0, t; }"
        : "=r"(a) : "l"(p));
    return a;
}

__device__ __forceinline__ void ldsm4(uint32_t a, uint32_t& r0, uint32_t& r1,
                                      uint32_t& r2, uint32_t& r3) {
    asm volatile("ldmatrix.sync.aligned.m8n8.x4.shared.b16 {%0,%1,%2,%3}, [%4];"
                 : "=r"(r0), "=r"(r1), "=r"(r2), "=r"(r3) : "r"(a));
}

// L2-only async copy (bypass L1 allocation): relieves L1 port for LDSM
__device__ __forceinline__ void cp16(uint32_t dst, const void* src, bool v) {
    int sz = v ? 16 : 0;
    asm volatile("cp.async.cg.shared.global [%0], [%1], 16, %2;"
                 :: "r"(dst), "l"(src), "r"(sz));
}

__device__ __forceinline__ void mma16816(float* a4, uint32_t a0, uint32_t a1,
                                         uint32_t a2, uint32_t a3,
                                         uint32_t b0, uint32_t b1) {
    asm volatile(
        "mma.sync.aligned.m16n8k16.row.col.f32.bf16.bf16.f32 "
        "{%0,%1,%2,%3}, {%4,%5,%6,%7}, {%8,%9}, {%0,%1,%2,%3};"
        : "+f"(a4[0]), "+f"(a4[1]), "+f"(a4[2]), "+f"(a4[3])
        : "r"(a0), "r"(a1), "r"(a2), "r"(a3), "r"(b0), "r"(b1));
}

// ---------------- fused weight split -----------------------------------------
__global__ void k_wsplit2(const float* __restrict__ w1, const float* __restrict__ w2,
                          __nv_bfloat16* __restrict__ h1, __nv_bfloat16* __restrict__ l1,
                          __nv_bfloat16* __restrict__ h2, __nv_bfloat16* __restrict__ l2,
                          int n1, int n2) {
    int i = blockIdx.x * blockDim.x + threadIdx.x;
    int half1 = n1 / 2;
    if (i < half1) {
        float2 v = ((const float2*)w1)[i];
        uint32_t hi, lo;
        bf16split2(v.x, v.y, hi, lo);
        ((uint32_t*)h1)[i] = hi;
        ((uint32_t*)l1)[i] = lo;
    } else {
        int j = i - half1;
        if (j >= n2 / 2) return;
        float2 v = ((const float2*)w2)[j];
        uint32_t hi, lo;
        bf16split2(v.x, v.y, hi, lo);
        ((uint32_t*)h2)[j] = hi;
        ((uint32_t*)l2)[j] = lo;
    }
}

// ---------------- fused embed -------------------------------------------------
__global__ void k_embed(const float* __restrict__ im8, const float* __restrict__ w,
                        const float* __restrict__ fb,
                        const float* __restrict__ s0, const float* __restrict__ s1,
                        const float* __restrict__ posemb) {
    int idx = blockIdx.x * blockDim.x + threadIdx.x;
    if (idx >= MR * DM) return;
    int d = idx % DM;
    int t = (idx / DM) % SEQ;
    int b = idx / (DM * SEQ);
    float v;
    if (t == 0) v = s0[d];
    else if (t == 65) v = s1[d];
    else {
        int src;
        int p = t - 66;
        if (t <= 64) src = t - 1;
        else src = ((p >> 6) >> 3) * 8 + ((p & 63) >> 3);
        const float* pix = im8 + (b * 64 + src) * 3;
        v = pix[0] * w[d] + pix[1] * w[DM + d] + pix[2] * w[2 * DM + d] + fb[d];
        if (t >= 66) v += posemb[(size_t)p * DM + d];
    }
    g_x[idx] = v;
}

// ---------------- layernorm -> bf16 hi/lo ------------------------------------
__global__ void k_ln(const float* __restrict__ lnw, const float* __restrict__ lnb) {
    __shared__ float red8[8];
    int row = blockIdx.x, tid = threadIdx.x;
    const float4* xr = (const float4*)(g_x + (size_t)row * DM);
    float4 v = xr[tid];
    float mean = blockSumN(v.x + v.y + v.z + v.w, red8, 8) * (1.f / DM);
    float dx = v.x - mean, dy = v.y - mean, dz = v.z - mean, dw = v.w - mean;
    float var = blockSumN(dx * dx + dy * dy + dz * dz + dw * dw, red8, 8) * (1.f / DM);
    float inv = rsqrtf(var + 1e-5f);
    float4 w4 = ((const float4*)lnw)[tid];
    float4 b4 = ((const float4*)lnb)[tid];
    float ox = dx * inv * w4.x + b4.x;
    float oy = dy * inv * w4.y + b4.y;
    float oz = dz * inv * w4.z + b4.z;
    float ow = dw * inv * w4.w + b4.w;
    uint32_t h0, l0, h1, l1;
    bf16split2(ox, oy, h0, l0);
    bf16split2(oz, ow, h1, l1);
    size_t o = (size_t)row * (DM / 4) + tid;
    ((uint2*)g_lnh)[o] = make_uint2(h0, h1);
    ((uint2*)g_lnl)[o] = make_uint2(l0, l1);
}

// ---------------- tensor-core GEMM (R15: .cg fills, f2 epilogue) --------------
#define BMT 128
#define BNT 128
#define BK2 32
#define RPITCH 80            // bytes per smem row (64 data + 16 pad)
#define ARRB (BMT * RPITCH)  // 10240 bytes per tile array
#define STAGEB (4 * ARRB)    // 40960 per stage
#define GSMEM (2 * STAGEB)   // 81920 total

__global__ void __launch_bounds__(256, 2)
k_gemm_bs(const __nv_bfloat16* __restrict__ Ah, const __nv_bfloat16* __restrict__ Al,
          const __nv_bfloat16* __restrict__ Bh, const __nv_bfloat16* __restrict__ Bl,
          float* __restrict__ C, int M, int N, int K, int accum) {
    extern __shared__ char smem[];
    const uint32_t sb = smem_u32(smem);
    const int tid = threadIdx.x;
    const int lane = tid & 31;
    const int wid = tid >> 5;
    const int warpM = wid >> 1;
    const int warpN = wid & 1;
    const int row0 = blockIdx.y * BMT;
    const int col0 = blockIdx.x * BNT;

    const int lr = lane >> 2, lc = lane & 3;
    const int grp = lane >> 3, lrow = lane & 7;
    const int a_mrow = (grp & 1) * 8 + lrow;
    const int a_koff = (grp >> 1) * 16;
    const int b_nrow = (grp >> 1) * 8 + lrow;
    const int b_koff = (grp & 1) * 16;

    float acc[2][8][4];
#pragma unroll
    for (int mt = 0; mt < 2; mt++)
#pragma unroll
        for (int nt = 0; nt < 8; nt++)
#pragma unroll
            for (int r = 0; r < 4; r++) acc[mt][nt][r] = 0.f;

    const int ntiles = K / BK2;
    const int ch0 = tid, ch1 = tid + 256;
    const int r0 = ch0 >> 2, c0 = ch0 & 3;
    const int r1 = ch1 >> 2, c1 = ch1 & 3;

    auto issue_stage = [&](int t, int buf) {
        int k0 = t * BK2;
        uint32_t s0 = sb + buf * STAGEB;
#pragma unroll
        for (int u = 0; u < 2; u++) {
            int r = u ? r1 : r0;
            int c = u ? c1 : c0;
            uint32_t doff = r * RPITCH + c * 16;
            int gra = row0 + r;
            bool va = gra < M;
            int grac = va ? gra : 0;
            size_t aoff = (size_t)grac * K + k0 + c * 8;
            cp16(s0 + doff, Ah + aoff, va);
            cp16(s0 + ARRB + doff, Al + aoff, va);
            int grb = col0 + r;
            bool vb = grb < N;
            int grbc = vb ? grb : 0;
            size_t boff = (size_t)grbc * K + k0 + c * 8;
            cp16(s0 + 2 * ARRB + doff, Bh + boff, vb);
            cp16(s0 + 3 * ARRB + doff, Bl + boff, vb);
        }
        asm volatile("cp.async.commit_group;");
    };

    issue_stage(0, 0);
    if (ntiles > 1) issue_stage(1, 1);
    else asm volatile("cp.async.commit_group;");

    for (int t = 0; t < ntiles; t++) {
        int buf = t & 1;
        if (t + 2 < ntiles) asm volatile("cp.async.wait_group 1;");
        else asm volatile("cp.async.wait_group 0;");
        __syncthreads();

        uint32_t sstage = sb + buf * STAGEB;
#pragma unroll
        for (int ks = 0; ks < 2; ks++) {
            uint32_t ah[2][4], al[2][4];
#pragma unroll
            for (int mt = 0; mt < 2; mt++) {
                uint32_t aoff = sstage + (warpM * 32 + mt * 16 + a_mrow) * RPITCH
                                + a_koff + ks * 32;
                ldsm4(aoff, ah[mt][0], ah[mt][1], ah[mt][2], ah[mt][3]);
                ldsm4(aoff + ARRB, al[mt][0], al[mt][1], al[mt][2], al[mt][3]);
            }
#pragma unroll
            for (int ntp = 0; ntp < 4; ntp++) {
                uint32_t boff = sstage + 2 * ARRB
                                + (warpN * 64 + ntp * 16 + b_nrow) * RPITCH
                                + b_koff + ks * 32;
                uint32_t bh[4], bl[4];
                ldsm4(boff, bh[0], bh[1], bh[2], bh[3]);
                ldsm4(boff + ARRB, bl[0], bl[1], bl[2], bl[3]);
#pragma unroll
                for (int par = 0; par < 2; par++) {
#pragma unroll
                    for (int mt = 0; mt < 2; mt++)
                        mma16816(acc[mt][ntp * 2 + par],
                                 al[mt][0], al[mt][1], al[mt][2], al[mt][3],
                                 bh[par * 2], bh[par * 2 + 1]);
                }
#pragma unroll
                for (int par = 0; par < 2; par++) {
#pragma unroll
                    for (int mt = 0; mt < 2; mt++)
                        mma16816(acc[mt][ntp * 2 + par],
                                 ah[mt][0], ah[mt][1], ah[mt][2], ah[mt][3],
                                 bl[par * 2], bl[par * 2 + 1]);
                }
#pragma unroll
                for (int par = 0; par < 2; par++) {
#pragma unroll
                    for (int mt = 0; mt < 2; mt++)
                        mma16816(acc[mt][ntp * 2 + par],
                                 ah[mt][0], ah[mt][1], ah[mt][2], ah[mt][3],
                                 bh[par * 2], bh[par * 2 + 1]);
                }
            }
        }
        __syncthreads();
        if (t + 2 < ntiles) issue_stage(t + 2, buf);
    }

    // epilogue: float2 stores
#pragma unroll
    for (int mt = 0; mt < 2; mt++) {
        int rbase = row0 + warpM * 32 + mt * 16 + lr;
#pragma unroll
        for (int nt = 0; nt < 8; nt++) {
            int cbase = col0 + warpN * 64 + nt * 8 + lc * 2;
            if (cbase + 1 < N) {
                if (rbase < M) {
                    float2* po = (float2*)&C[(size_t)rbase * N + cbase];
                    float2 vv = make_float2(acc[mt][nt][0], acc[mt][nt][1]);
                    if (accum) { float2 o = *po; vv.x += o.x; vv.y += o.y; }
                    *po = vv;
                }
                if (rbase + 8 < M) {
                    float2* po = (float2*)&C[(size_t)(rbase + 8) * N + cbase];
                    float2 vv = make_float2(acc[mt][nt][2], acc[mt][nt][3]);
                    if (accum) { float2 o = *po; vv.x += o.x; vv.y += o.y; }
                    *po = vv;
                }
            } else if (cbase < N) {
                if (rbase < M) {
                    size_t o = (size_t)rbase * N + cbase;
                    C[o] = accum ? (C[o] + acc[mt][nt][0]) : acc[mt][nt][0];
                }
                if (rbase + 8 < M) {
                    size_t o = (size_t)(rbase + 8) * N + cbase;
                    C[o] = accum ? (C[o] + acc[mt][nt][2]) : acc[mt][nt][2];
                }
            }
        }
    }
}

// ---------------- dt / dA ---------------------------------------------------
__global__ void k_dt(const float* __restrict__ dtb, const float* __restrict__ Alog) {
    int idx = blockIdx.x * blockDim.x + threadIdx.x;
    if (idx >= MR * NH) return;
    int h = idx % NH;
    int row = idx / NH;
    float v = g_zx[(size_t)row * DIP + (DIP - NH) + h] + dtb[h];
    float sp = (v > 20.f) ? v : log1pf(expf(v));
    float A = -expf(Alog[h]);
    g_dt[idx] = sp;
    g_dA[idx] = expf(sp * A);
}

// ---------------- causal depthwise conv: smem-tiled ---------------------------
#define CTS 64
#define CCS 64
__global__ void k_conv(const float* __restrict__ cw, const float* __restrict__ cb) {
    __shared__ float st[CTS + 3][CCS];
    int c0 = blockIdx.x * CCS;
    int t0 = blockIdx.y * CTS;
    int b = blockIdx.z;
    int tid = threadIdx.x;
    for (int i = tid; i < (CTS + 3) * (CCS / 4); i += 256) {
        int rr = i >> 4, cc = (i & 15) * 4;
        int t = t0 - 3 + rr;
        float4 v = make_float4(0.f, 0.f, 0.f, 0.f);
        if (t >= 0 && t < SEQ)
            v = *(const float4*)&g_zx[((size_t)(b * SEQ + t)) * DIP + DI + c0 + cc];
        *(float4*)&st[rr][cc] = v;
    }
    __syncthreads();
    int cc = (tid & 15) * 4;
    int tt = (tid >> 4) * 4;
    float4 w0 = *(const float4*)(cw + (c0 + cc) * 4);
    float4 w1 = *(const float4*)(cw + (c0 + cc + 1) * 4);
    float4 w2 = *(const float4*)(cw + (c0 + cc + 2) * 4);
    float4 w3 = *(const float4*)(cw + (c0 + cc + 3) * 4);
    float4 bias = *(const float4*)(cb + c0 + cc);
#pragma unroll
    for (int u = 0; u < 4; u++) {
        int t = t0 + tt + u;
        if (t >= SEQ) break;
        float4 xv0 = *(const float4*)&st[tt + u + 0][cc];
        float4 xv1 = *(const float4*)&st[tt + u + 1][cc];
        float4 xv2 = *(const float4*)&st[tt + u + 2][cc];
        float4 xv3 = *(const float4*)&st[tt + u + 3][cc];
        float4 acc = bias;
        acc.x += xv0.x * w0.x + xv1.x * w0.y + xv2.x * w0.z + xv3.x * w0.w;
        acc.y += xv0.y * w1.x + xv1.y * w1.y + xv2.y * w1.z + xv3.y * w1.w;
        acc.z += xv0.z * w2.x + xv1.z * w2.y + xv2.z * w2.z + xv3.z * w2.w;
        acc.w += xv0.w * w3.x + xv1.w * w3.y + xv2.w * w3.z + xv3.w * w3.w;
        float4 o = make_float4(siluf(acc.x), siluf(acc.y), siluf(acc.z), siluf(acc.w));
        *(float4*)&g_xBC[((size_t)(b * SEQ + t)) * CONV_DIM + c0 + cc] = o;
    }
}

// ---------------- chunked scan: phase A (256 thr, 4 p-blocks) ----------------
__global__ void k_scanA(const float* __restrict__ Dp) {
    __shared__ float sx[64][32];
    __shared__ float sB[64][64];
    __shared__ float sC[64][64];
    __shared__ float sdA[64];
    __shared__ float sdt[64];
    int c = blockIdx.x >> 2, pblk = blockIdx.x & 3;
    int h = blockIdx.y, b = blockIdx.z;
    int tid = threadIdx.x;
    int pl = tid >> 3, ng = tid & 7, n0 = ng * 8;
    int p = pblk * 32 + pl;
    float s[8];
#pragma unroll
    for (int j = 0; j < 8; j++) s[j] = 0.f;
    float approd = 1.f;
    float Dh = Dp[h];
    size_t baseRow = (size_t)b * SEQ;
    int xoff = h * HD + pblk * 32;
    int t0base = c * LCH;
    int tlim = min(SEQ, t0base + LCH);
    for (int t0 = t0base; t0 < tlim; t0 += 64) {
        int cnt = min(64, tlim - t0);
        for (int i = tid; i < cnt * 8; i += 256) {
            int q = i >> 3, ii = i & 7;
            ((float4*)sx[q])[ii] =
                *(const float4*)&g_xBC[(baseRow + t0 + q) * CONV_DIM + xoff + ii * 4];
        }
        for (int i = tid; i < cnt * 16; i += 256) {
            int q = i >> 4, ii = i & 15;
            ((float4*)sB[q])[ii] =
                *(const float4*)&g_xBC[(baseRow + t0 + q) * CONV_DIM + DI + ii * 4];
        }
        for (int i = tid; i < cnt * 16; i += 256) {
            int q = i >> 4, ii = i & 15;
            ((float4*)sC[q])[ii] =
                *(const float4*)&g_xBC[(baseRow + t0 + q) * CONV_DIM + DI + DSTATE + ii * 4];
        }
        for (int i = tid; i < cnt; i += 256) {
            sdA[i] = g_dA[(baseRow + t0 + i) * NH + h];
            sdt[i] = g_dt[(baseRow + t0 + i) * NH + h];
        }
        __syncthreads();
        for (int q = 0; q < cnt; q++) {
            float dA = sdA[q];
            approd *= dA;
            float xp = sx[q][pl];
            float a = sdt[q] * xp;
            float4 bb0 = *(const float4*)&sB[q][n0];
            float4 bb1 = *(const float4*)&sB[q][n0 + 4];
            float4 cc0 = *(const float4*)&sC[q][n0];
            float4 cc1 = *(const float4*)&sC[q][n0 + 4];
            float yp;
            s[0] = s[0] * dA + a * bb0.x; yp  = s[0] * cc0.x;
            s[1] = s[1] * dA + a * bb0.y; yp += s[1] * cc0.y;
            s[2] = s[2] * dA + a * bb0.z; yp += s[2] * cc0.z;
            s[3] = s[3] * dA + a * bb0.w; yp += s[3] * cc0.w;
            s[4] = s[4] * dA + a * bb1.x; yp += s[4] * cc1.x;
            s[5] = s[5] * dA + a * bb1.y; yp += s[5] * cc1.y;
            s[6] = s[6] * dA + a * bb1.z; yp += s[6] * cc1.z;
            s[7] = s[7] * dA + a * bb1.w; yp += s[7] * cc1.w;
            yp += __shfl_xor_sync(0xffffffffu, yp, 1);
            yp += __shfl_xor_sync(0xffffffffu, yp, 2);
            yp += __shfl_xor_sync(0xffffffffu, yp, 4);
            if (ng == 0)
                g_y[(baseRow + t0 + q) * DI + h * HD + p] = yp + Dh * xp;
        }
        __syncthreads();
    }
    size_t so = ((((size_t)(b * NH + h)) * TCH + c) * HD + p) * DSTATE + n0;
    *(float4*)&g_S[so]     = make_float4(s[0], s[1], s[2], s[3]);
    *(float4*)&g_S[so + 4] = make_float4(s[4], s[5], s[6], s[7]);
    if (tid == 0) g_P[(b * NH + h) * TCH + c] = approd;
}

// ---------------- chunked scan: phase B --------------------------------------
__global__ void k_scanB() {
    int idx = blockIdx.x * blockDim.x + threadIdx.x;
    if (idx >= B_SZ * NH * HD * DSTATE) return;
    int bh = idx >> 13;
    float H = 0.f;
#pragma unroll 1
    for (int c = 0; c < TCH; c++) {
        size_t o = (((size_t)bh * TCH + c) << 13) + (idx & 8191);
        g_Hb[o] = H;
        H = g_P[bh * TCH + c] * H + g_S[o];
    }
}

// ---------------- chunked scan: phase C (256 thr, 4 p-blocks) ----------------
__global__ void k_scanC() {
    __shared__ float sC[64][64];
    __shared__ float sdA[64];
    int c = (blockIdx.x >> 2) + 1, pblk = blockIdx.x & 3;
    int h = blockIdx.y, b = blockIdx.z;
    int tid = threadIdx.x;
    int pl = tid >> 3, ng = tid & 7, n0 = ng * 8;
    int p = pblk * 32 + pl;
    size_t baseRow = (size_t)b * SEQ;
    size_t ho = ((((size_t)(b * NH + h)) * TCH + c) * HD + p) * DSTATE + n0;
    float4 H0 = *(const float4*)&g_Hb[ho];
    float4 H1 = *(const float4*)&g_Hb[ho + 4];
    float ap = 1.f;
    int t0base = c * LCH;
    int tlim = min(SEQ, t0base + LCH);
    for (int t0 = t0base; t0 < tlim; t0 += 64) {
        int cnt = min(64, tlim - t0);
        for (int i = tid; i < cnt * 16; i += 256) {
            int q = i >> 4, ii = i & 15;
            ((float4*)sC[q])[ii] =
                *(const float4*)&g_xBC[(baseRow + t0 + q) * CONV_DIM + DI + DSTATE + ii * 4];
        }
        for (int i = tid; i < cnt; i += 256)
            sdA[i] = g_dA[(baseRow + t0 + i) * NH + h];
        __syncthreads();
        for (int q = 0; q < cnt; q++) {
            ap *= sdA[q];
            if (ap < 1e-37f) { ap = 0.f; break; }
            float4 cc0 = *(const float4*)&sC[q][n0];
            float4 cc1 = *(const float4*)&sC[q][n0 + 4];
            float d = H0.x * cc0.x + H0.y * cc0.y + H0.z * cc0.z + H0.w * cc0.w
                    + H1.x * cc1.x + H1.y * cc1.y + H1.z * cc1.z + H1.w * cc1.w;
            d += __shfl_xor_sync(0xffffffffu, d, 1);
            d += __shfl_xor_sync(0xffffffffu, d, 2);
            d += __shfl_xor_sync(0xffffffffu, d, 4);
            if (ng == 0)
                g_y[(baseRow + t0 + q) * DI + h * HD + p] += ap * d;
        }
        __syncthreads();
        if (ap == 0.f) break;
    }
}

// ---------------- gate + RMSNorm -> bf16 hi/lo --------------------------------
__global__ void k_gaterms(const float* __restrict__ rmsw) {
    __shared__ float red8[8];
    int row = blockIdx.x, tid = threadIdx.x;
    const float4* zr = (const float4*)(g_zx + (size_t)row * DIP);
    const float4* yr = (const float4*)(g_y + (size_t)row * DI);
    float4 z0 = zr[tid], z1 = zr[tid + 256];
    float4 y0 = yr[tid], y1 = yr[tid + 256];
    float4 g0, g1;
    g0.x = y0.x * siluf(z0.x); g0.y = y0.y * siluf(z0.y);
    g0.z = y0.z * siluf(z0.z); g0.w = y0.w * siluf(z0.w);
    g1.x = y1.x * siluf(z1.x); g1.y = y1.y * siluf(z1.y);
    g1.z = y1.z * siluf(z1.z); g1.w = y1.w * siluf(z1.w);
    float ss = g0.x * g0.x + g0.y * g0.y + g0.z * g0.z + g0.w * g0.w
             + g1.x * g1.x + g1.y * g1.y + g1.z * g1.z + g1.w * g1.w;
    float tot = blockSumN(ss, red8, 8);
    float inv = rsqrtf(tot * (1.f / DI) + 1e-5f);
    float4 w0 = ((const float4*)rmsw)[tid], w1 = ((const float4*)rmsw)[tid + 256];
    g0.x *= inv * w0.x; g0.y *= inv * w0.y; g0.z *= inv * w0.z; g0.w *= inv * w0.w;
    g1.x *= inv * w1.x; g1.y *= inv * w1.y; g1.z *= inv * w1.z; g1.w *= inv * w1.w;
    uint32_t h0, l0, h1, l1;
    size_t o = (size_t)row * (DI / 4) + tid;
    bf16split2(g0.x, g0.y, h0, l0);
    bf16split2(g0.z, g0.w, h1, l1);
    ((uint2*)g_yh)[o] = make_uint2(h0, h1);
    ((uint2*)g_yl)[o] = make_uint2(l0, l1);
    bf16split2(g1.x, g1.y, h0, l0);
    bf16split2(g1.z, g1.w, h1, l1);
    ((uint2*)g_yh)[o + 256] = make_uint2(h0, h1);
    ((uint2*)g_yl)[o + 256] = make_uint2(l0, l1);
}

// ---------------- output head: warp per pixel --------------------------------
__global__ void k_head(const float* __restrict__ w, const float* __restrict__ bias,
                       const float* __restrict__ im64, float* __restrict__ out,
                       int out_size) {
    __shared__ float sw[DM * 3];
    int tid = threadIdx.x;
    for (int i = tid; i < DM * 3; i += 256) sw[i] = w[i];
    __syncthreads();
    int lane = tid & 31, wid = tid >> 5;
    int r = blockIdx.x * 8 + wid;
    int b = r / 4096, p = r % 4096;
    const float* xr = g_x + ((size_t)(b * SEQ) + 66 + p) * DM;
    float a0 = 0.f, a1 = 0.f, a2 = 0.f;
    for (int i = lane; i < DM; i += 32) {
        float v = xr[i];
        a0 += v * sw[i * 3 + 0];
        a1 += v * sw[i * 3 + 1];
        a2 += v * sw[i * 3 + 2];
    }
#pragma unroll
    for (int o = 16; o; o >>= 1) {
        a0 += __shfl_xor_sync(0xffffffffu, a0, o);
        a1 += __shfl_xor_sync(0xffffffffu, a1, o);
        a2 += __shfl_xor_sync(0xffffffffu, a2, o);
    }
    if (lane == 0) {
        float y0 = a0 + bias[0], y1 = a1 + bias[1], y2 = a2 + bias[2];
        const float* im = im64 + (size_t)r * 3;
        float e0 = y0 - im[0], e1 = y1 - im[1], e2 = y2 - im[2];
        g_part[r] = e0 * e0 + e1 * e1 + e2 * e2;
        if (out_size >= YHAT_ELEMS) {
            out[(size_t)r * 3 + 0] = y0;
            out[(size_t)r * 3 + 1] = y1;
            out[(size_t)r * 3 + 2] = y2;
        }
    }
}

__global__ void k_loss(float* __restrict__ out, int out_size) {
    __shared__ float red8[8];
    float s = 0.f;
    for (int i = threadIdx.x; i < NPIX; i += 256) s += g_part[i];
    float tot = blockSumN(s, red8, 8);
    if (threadIdx.x == 0) {
        float loss = tot * (1.f / (float)YHAT_ELEMS);
        if (out_size <= 1) out[0] = loss;
        else if (out_size > YHAT_ELEMS) out[YHAT_ELEMS] = loss;
    }
}

// ---------------- driver -----------------------------------------------------
extern "C" void kernel_launch(void* const* d_in, const int* in_sizes, int n_in,
                              void* d_out, int out_size) {
    const float* im8        = (const float*)d_in[0];
    const float* im64       = (const float*)d_in[1];
    const float* from_rgb_w = (const float*)d_in[2];
    const float* from_rgb_b = (const float*)d_in[3];
    const float* to_rgb_w   = (const float*)d_in[4];
    const float* to_rgb_b   = (const float*)d_in[5];
    const float* s0         = (const float*)d_in[6];
    const float* s1         = (const float*)d_in[7];
    const float* posemb     = (const float*)d_in[8];
    const float* ln_w       = (const float*)d_in[9];
    const float* ln_b       = (const float*)d_in[10];
    const float* in_proj_w  = (const float*)d_in[11];
    const float* conv_w     = (const float*)d_in[12];
    const float* conv_b     = (const float*)d_in[13];
    const float* dt_bias    = (const float*)d_in[14];
    const float* A_log      = (const float*)d_in[15];
    const float* Dp         = (const float*)d_in[16];
    const float* rms_w      = (const float*)d_in[17];
    const float* out_proj_w = (const float*)d_in[18];
    float* out = (float*)d_out;

    float *p_x, *p_zx;
    cudaGetSymbolAddress((void**)&p_x, g_x);
    cudaGetSymbolAddress((void**)&p_zx, g_zx);
    __nv_bfloat16 *p_lnh, *p_lnl, *p_yh, *p_yl, *p_w1h, *p_w1l, *p_w2h, *p_w2l;
    cudaGetSymbolAddress((void**)&p_lnh, g_lnh);
    cudaGetSymbolAddress((void**)&p_lnl, g_lnl);
    cudaGetSymbolAddress((void**)&p_yh, g_yh);
    cudaGetSymbolAddress((void**)&p_yl, g_yl);
    cudaGetSymbolAddress((void**)&p_w1h, g_w1h);
    cudaGetSymbolAddress((void**)&p_w1l, g_w1l);
    cudaGetSymbolAddress((void**)&p_w2h, g_w2h);
    cudaGetSymbolAddress((void**)&p_w2l, g_w2l);

    cudaFuncSetAttribute(k_gemm_bs, cudaFuncAttributeMaxDynamicSharedMemorySize,
                         GSMEM);

    // launch #1
    {
        int n1 = NL * DIP * DM, n2 = NL * DM * DI;
        int tot = n1 / 2 + n2 / 2;
        k_wsplit2<<<(tot + 255) / 256, 256>>>(in_proj_w, out_proj_w,
                                              p_w1h, p_w1l, p_w2h, p_w2l, n1, n2);
    }
    // launch #2
    k_embed<<<(MR * DM + 255) / 256, 256>>>(im8, from_rgb_w, from_rgb_b,
                                            s0, s1, posemb);
    // launch #3
    k_ln<<<MR, 256>>>(ln_w, ln_b);

    // launch #4: MEASUREMENT dummy — out_proj-shaped GEMM (M=MR,N=DM,K=DI).
    // Inputs: stale-but-deterministic g_yh/g_yl + layer-0 w2; output g_zx is
    // fully overwritten by the real in_proj GEMM (launch #5). ncu captures
    // launch #4, revealing the true out_proj duration + pipe mix.
    {
        dim3 gd((DM + BNT - 1) / BNT, (MR + BMT - 1) / BMT);
        k_gemm_bs<<<gd, 256, GSMEM>>>(p_yh, p_yl, p_w2h, p_w2l,
                                      p_zx, MR, DM, DI, 0);
    }

    for (int l = 0; l < NL; l++) {
        if (l > 0) k_ln<<<MR, 256>>>(ln_w + l * DM, ln_b + l * DM);

        dim3 g1((DIP + BNT - 1) / BNT, (MR + BMT - 1) / BMT);
        k_gemm_bs<<<g1, 256, GSMEM>>>(p_lnh, p_lnl,
                                      p_w1h + (size_t)l * DIP * DM,
                                      p_w1l + (size_t)l * DIP * DM,
                                      p_zx, MR, DIP, DM, 0);

        k_dt<<<(MR * NH + 255) / 256, 256>>>(dt_bias + l * NH, A_log + l * NH);
        dim3 gconv(CONV_DIM / CCS, (SEQ + CTS - 1) / CTS, B_SZ);
        k_conv<<<gconv, 256>>>(conv_w + l * CONV_DIM * 4, conv_b + l * CONV_DIM);

        dim3 gA(TCH * 4, NH, B_SZ);
        k_scanA<<<gA, 256>>>(Dp + l * NH);
        k_scanB<<<(B_SZ * NH * HD * DSTATE + 255) / 256, 256>>>();
        dim3 gC((TCH - 1) * 4, NH, B_SZ);
        k_scanC<<<gC, 256>>>();

        k_gaterms<<<MR, 256>>>(rms_w + l * DI);

        dim3 g2((DM + BNT - 1) / BNT, (MR + BMT - 1) / BMT);
        k_gemm_bs<<<g2, 256, GSMEM>>>(p_yh, p_yl,
                                      p_w2h + (size_t)l * DM * DI,
                                      p_w2l + (size_t)l * DM * DI,
                                      p_x, MR, DM, DI, 1);
    }

    k_head<<<NPIX / 8, 256>>>(to_rgb_w, to_rgb_b, im64, out, out_size);
    k_loss<<<1, 256>>>(out, out_size);
}

// round 17
// speedup vs baseline: 1.0477x; 1.0477x over previous
#include <cuda_runtime.h>
#include <cuda_bf16.h>
#include <math.h>
#include <stdint.h>

#define B_SZ 2
#define SEQ 4162
#define DM 1024
#define DI 2048
#define DSTATE 64
#define HD 128
#define NH 16
#define NL 4
#define CONV_DIM 2176
#define DIP 4240
#define MR (B_SZ*SEQ)          // 8324 rows
#define NPIX (B_SZ*4096)       // 8192
#define YHAT_ELEMS (NPIX*3)    // 24576
#define LCH 256                // scan chunk length
#define TCH 17                 // ceil(SEQ/LCH)

// ---------------- scratch (static device allocations; no cudaMalloc) -------
__device__ float g_x[(size_t)MR*DM];        // residual stream
__device__ float g_zx[(size_t)MR*DIP];      // in_proj output
__device__ float g_xBC[(size_t)MR*CONV_DIM];// conv+silu output
__device__ float g_y[(size_t)MR*DI];        // scan output
__device__ float g_dt[MR*NH];
__device__ float g_dA[MR*NH];
__device__ float g_part[NPIX];
// chunked-scan state buffers
__device__ float g_S[(size_t)B_SZ*NH*TCH*HD*DSTATE];
__device__ float g_Hb[(size_t)B_SZ*NH*TCH*HD*DSTATE];
__device__ float g_P[B_SZ*NH*TCH];
// bf16 hi/lo split buffers
__device__ __nv_bfloat16 g_lnh[(size_t)MR*DM];
__device__ __nv_bfloat16 g_lnl[(size_t)MR*DM];
__device__ __nv_bfloat16 g_yh[(size_t)MR*DI];
__device__ __nv_bfloat16 g_yl[(size_t)MR*DI];
__device__ __nv_bfloat16 g_w1h[(size_t)NL*DIP*DM];
__device__ __nv_bfloat16 g_w1l[(size_t)NL*DIP*DM];
__device__ __nv_bfloat16 g_w2h[(size_t)NL*DM*DI];
__device__ __nv_bfloat16 g_w2l[(size_t)NL*DM*DI];

// ---------------- helpers ---------------------------------------------------
__device__ __forceinline__ float siluf(float x) { return x / (1.f + expf(-x)); }

__device__ __forceinline__ float blockSumN(float v, float* red, int nwarp) {
    int lane = threadIdx.x & 31, wid = threadIdx.x >> 5;
#pragma unroll
    for (int o = 16; o; o >>= 1) v += __shfl_xor_sync(0xffffffffu, v, o);
    if (lane == 0) red[wid] = v;
    __syncthreads();
    float r = 0.f;
    for (int i = 0; i < nwarp; i++) r += red[i];
    __syncthreads();
    return r;
}

__device__ __forceinline__ void bf16split2(float x, float y, uint32_t& hi, uint32_t& lo) {
    __nv_bfloat162 h = __floats2bfloat162_rn(x, y);
    uint32_t hw = *reinterpret_cast<uint32_t*>(&h);
    float hx = __uint_as_float(hw << 16);
    float hy = __uint_as_float(hw & 0xffff0000u);
    __nv_bfloat162 l = __floats2bfloat162_rn(x - hx, y - hy);
    hi = hw;
    lo = *reinterpret_cast<uint32_t*>(&l);
}

__device__ __forceinline__ uint32_t smem_u32(const void* p) {
    uint32_t a;
    asm("{ .reg .u64 t; cvta.to.shared.u64 t, %1; cvt.u32.u64 %0, t; }"
        : "=r"(a) : "l"(p));
    return a;
}

__device__ __forceinline__ void ldsm4(uint32_t a, uint32_t& r0, uint32_t& r1,
                                      uint32_t& r2, uint32_t& r3) {
    asm volatile("ldmatrix.sync.aligned.m8n8.x4.shared.b16 {%0,%1,%2,%3}, [%4];"
                 : "=r"(r0), "=r"(r1), "=r"(r2), "=r"(r3) : "r"(a));
}

// L2-only async copy (bypass L1 allocation): relieves L1 port for LDSM
__device__ __forceinline__ void cp16(uint32_t dst, const void* src, bool v) {
    int sz = v ? 16 : 0;
    asm volatile("cp.async.cg.shared.global [%0], [%1], 16, %2;"
                 :: "r"(dst), "l"(src), "r"(sz));
}

__device__ __forceinline__ void mma16816(float* a4, uint32_t a0, uint32_t a1,
                                         uint32_t a2, uint32_t a3,
                                         uint32_t b0, uint32_t b1) {
    asm volatile(
        "mma.sync.aligned.m16n8k16.row.col.f32.bf16.bf16.f32 "
        "{%0,%1,%2,%3}, {%4,%5,%6,%7}, {%8,%9}, {%0,%1,%2,%3};"
        : "+f"(a4[0]), "+f"(a4[1]), "+f"(a4[2]), "+f"(a4[3])
        : "r"(a0), "r"(a1), "r"(a2), "r"(a3), "r"(b0), "r"(b1));
}

// ---------------- fused weight split -----------------------------------------
__global__ void k_wsplit2(const float* __restrict__ w1, const float* __restrict__ w2,
                          __nv_bfloat16* __restrict__ h1, __nv_bfloat16* __restrict__ l1,
                          __nv_bfloat16* __restrict__ h2, __nv_bfloat16* __restrict__ l2,
                          int n1, int n2) {
    int i = blockIdx.x * blockDim.x + threadIdx.x;
    int half1 = n1 / 2;
    if (i < half1) {
        float2 v = ((const float2*)w1)[i];
        uint32_t hi, lo;
        bf16split2(v.x, v.y, hi, lo);
        ((uint32_t*)h1)[i] = hi;
        ((uint32_t*)l1)[i] = lo;
    } else {
        int j = i - half1;
        if (j >= n2 / 2) return;
        float2 v = ((const float2*)w2)[j];
        uint32_t hi, lo;
        bf16split2(v.x, v.y, hi, lo);
        ((uint32_t*)h2)[j] = hi;
        ((uint32_t*)l2)[j] = lo;
    }
}

// ---------------- fused embed -------------------------------------------------
__global__ void k_embed(const float* __restrict__ im8, const float* __restrict__ w,
                        const float* __restrict__ fb,
                        const float* __restrict__ s0, const float* __restrict__ s1,
                        const float* __restrict__ posemb) {
    int idx = blockIdx.x * blockDim.x + threadIdx.x;
    if (idx >= MR * DM) return;
    int d = idx % DM;
    int t = (idx / DM) % SEQ;
    int b = idx / (DM * SEQ);
    float v;
    if (t == 0) v = s0[d];
    else if (t == 65) v = s1[d];
    else {
        int src;
        int p = t - 66;
        if (t <= 64) src = t - 1;
        else src = ((p >> 6) >> 3) * 8 + ((p & 63) >> 3);
        const float* pix = im8 + (b * 64 + src) * 3;
        v = pix[0] * w[d] + pix[1] * w[DM + d] + pix[2] * w[2 * DM + d] + fb[d];
        if (t >= 66) v += posemb[(size_t)p * DM + d];
    }
    g_x[idx] = v;
}

// ---------------- layernorm -> bf16 hi/lo ------------------------------------
__global__ void k_ln(const float* __restrict__ lnw, const float* __restrict__ lnb) {
    __shared__ float red8[8];
    int row = blockIdx.x, tid = threadIdx.x;
    const float4* xr = (const float4*)(g_x + (size_t)row * DM);
    float4 v = xr[tid];
    float mean = blockSumN(v.x + v.y + v.z + v.w, red8, 8) * (1.f / DM);
    float dx = v.x - mean, dy = v.y - mean, dz = v.z - mean, dw = v.w - mean;
    float var = blockSumN(dx * dx + dy * dy + dz * dz + dw * dw, red8, 8) * (1.f / DM);
    float inv = rsqrtf(var + 1e-5f);
    float4 w4 = ((const float4*)lnw)[tid];
    float4 b4 = ((const float4*)lnb)[tid];
    float ox = dx * inv * w4.x + b4.x;
    float oy = dy * inv * w4.y + b4.y;
    float oz = dz * inv * w4.z + b4.z;
    float ow = dw * inv * w4.w + b4.w;
    uint32_t h0, l0, h1, l1;
    bf16split2(ox, oy, h0, l0);
    bf16split2(oz, ow, h1, l1);
    size_t o = (size_t)row * (DM / 4) + tid;
    ((uint2*)g_lnh)[o] = make_uint2(h0, h1);
    ((uint2*)g_lnl)[o] = make_uint2(l0, l1);
}

// ---------------- tensor-core GEMM (.cg fills, f2 epilogue, strided C) -------
#define BMT 128
#define BNT 128
#define BK2 32
#define RPITCH 80            // bytes per smem row (64 data + 16 pad)
#define ARRB (BMT * RPITCH)  // 10240 bytes per tile array
#define STAGEB (4 * ARRB)    // 40960 per stage
#define GSMEM (2 * STAGEB)   // 81920 total

__global__ void __launch_bounds__(256, 2)
k_gemm_bs(const __nv_bfloat16* __restrict__ Ah, const __nv_bfloat16* __restrict__ Al,
          const __nv_bfloat16* __restrict__ Bh, const __nv_bfloat16* __restrict__ Bl,
          float* __restrict__ C, int M, int N, int K, int ldC, int colOff,
          int accum) {
    extern __shared__ char smem[];
    const uint32_t sb = smem_u32(smem);
    const int tid = threadIdx.x;
    const int lane = tid & 31;
    const int wid = tid >> 5;
    const int warpM = wid >> 1;
    const int warpN = wid & 1;
    const int row0 = blockIdx.y * BMT;
    const int col0 = blockIdx.x * BNT;

    const int lr = lane >> 2, lc = lane & 3;
    const int grp = lane >> 3, lrow = lane & 7;
    const int a_mrow = (grp & 1) * 8 + lrow;
    const int a_koff = (grp >> 1) * 16;
    const int b_nrow = (grp >> 1) * 8 + lrow;
    const int b_koff = (grp & 1) * 16;

    float acc[2][8][4];
#pragma unroll
    for (int mt = 0; mt < 2; mt++)
#pragma unroll
        for (int nt = 0; nt < 8; nt++)
#pragma unroll
            for (int r = 0; r < 4; r++) acc[mt][nt][r] = 0.f;

    const int ntiles = K / BK2;
    const int ch0 = tid, ch1 = tid + 256;
    const int r0 = ch0 >> 2, c0 = ch0 & 3;
    const int r1 = ch1 >> 2, c1 = ch1 & 3;

    auto issue_stage = [&](int t, int buf) {
        int k0 = t * BK2;
        uint32_t s0 = sb + buf * STAGEB;
#pragma unroll
        for (int u = 0; u < 2; u++) {
            int r = u ? r1 : r0;
            int c = u ? c1 : c0;
            uint32_t doff = r * RPITCH + c * 16;
            int gra = row0 + r;
            bool va = gra < M;
            int grac = va ? gra : 0;
            size_t aoff = (size_t)grac * K + k0 + c * 8;
            cp16(s0 + doff, Ah + aoff, va);
            cp16(s0 + ARRB + doff, Al + aoff, va);
            int grb = col0 + r;
            bool vb = grb < N;
            int grbc = vb ? grb : 0;
            size_t boff = (size_t)grbc * K + k0 + c * 8;
            cp16(s0 + 2 * ARRB + doff, Bh + boff, vb);
            cp16(s0 + 3 * ARRB + doff, Bl + boff, vb);
        }
        asm volatile("cp.async.commit_group;");
    };

    issue_stage(0, 0);
    if (ntiles > 1) issue_stage(1, 1);
    else asm volatile("cp.async.commit_group;");

    for (int t = 0; t < ntiles; t++) {
        int buf = t & 1;
        if (t + 2 < ntiles) asm volatile("cp.async.wait_group 1;");
        else asm volatile("cp.async.wait_group 0;");
        __syncthreads();

        uint32_t sstage = sb + buf * STAGEB;
#pragma unroll
        for (int ks = 0; ks < 2; ks++) {
            uint32_t ah[2][4], al[2][4];
#pragma unroll
            for (int mt = 0; mt < 2; mt++) {
                uint32_t aoff = sstage + (warpM * 32 + mt * 16 + a_mrow) * RPITCH
                                + a_koff + ks * 32;
                ldsm4(aoff, ah[mt][0], ah[mt][1], ah[mt][2], ah[mt][3]);
                ldsm4(aoff + ARRB, al[mt][0], al[mt][1], al[mt][2], al[mt][3]);
            }
#pragma unroll
            for (int ntp = 0; ntp < 4; ntp++) {
                uint32_t boff = sstage + 2 * ARRB
                                + (warpN * 64 + ntp * 16 + b_nrow) * RPITCH
                                + b_koff + ks * 32;
                uint32_t bh[4], bl[4];
                ldsm4(boff, bh[0], bh[1], bh[2], bh[3]);
                ldsm4(boff + ARRB, bl[0], bl[1], bl[2], bl[3]);
#pragma unroll
                for (int par = 0; par < 2; par++) {
#pragma unroll
                    for (int mt = 0; mt < 2; mt++)
                        mma16816(acc[mt][ntp * 2 + par],
                                 al[mt][0], al[mt][1], al[mt][2], al[mt][3],
                                 bh[par * 2], bh[par * 2 + 1]);
                }
#pragma unroll
                for (int par = 0; par < 2; par++) {
#pragma unroll
                    for (int mt = 0; mt < 2; mt++)
                        mma16816(acc[mt][ntp * 2 + par],
                                 ah[mt][0], ah[mt][1], ah[mt][2], ah[mt][3],
                                 bl[par * 2], bl[par * 2 + 1]);
                }
#pragma unroll
                for (int par = 0; par < 2; par++) {
#pragma unroll
                    for (int mt = 0; mt < 2; mt++)
                        mma16816(acc[mt][ntp * 2 + par],
                                 ah[mt][0], ah[mt][1], ah[mt][2], ah[mt][3],
                                 bh[par * 2], bh[par * 2 + 1]);
                }
            }
        }
        __syncthreads();
        if (t + 2 < ntiles) issue_stage(t + 2, buf);
    }

    // epilogue: float2 stores into strided C
#pragma unroll
    for (int mt = 0; mt < 2; mt++) {
        int rbase = row0 + warpM * 32 + mt * 16 + lr;
#pragma unroll
        for (int nt = 0; nt < 8; nt++) {
            int cbase = col0 + warpN * 64 + nt * 8 + lc * 2;
            if (cbase + 1 < N) {
                if (rbase < M) {
                    float2* po = (float2*)&C[(size_t)rbase * ldC + colOff + cbase];
                    float2 vv = make_float2(acc[mt][nt][0], acc[mt][nt][1]);
                    if (accum) { float2 o = *po; vv.x += o.x; vv.y += o.y; }
                    *po = vv;
                }
                if (rbase + 8 < M) {
                    float2* po = (float2*)&C[(size_t)(rbase + 8) * ldC + colOff + cbase];
                    float2 vv = make_float2(acc[mt][nt][2], acc[mt][nt][3]);
                    if (accum) { float2 o = *po; vv.x += o.x; vv.y += o.y; }
                    *po = vv;
                }
            } else if (cbase < N) {
                if (rbase < M) {
                    size_t o = (size_t)rbase * ldC + colOff + cbase;
                    C[o] = accum ? (C[o] + acc[mt][nt][0]) : acc[mt][nt][0];
                }
                if (rbase + 8 < M) {
                    size_t o = (size_t)(rbase + 8) * ldC + colOff + cbase;
                    C[o] = accum ? (C[o] + acc[mt][nt][2]) : acc[mt][nt][2];
                }
            }
        }
    }
}

// ---------------- dt / dA ---------------------------------------------------
__global__ void k_dt(const float* __restrict__ dtb, const float* __restrict__ Alog) {
    int idx = blockIdx.x * blockDim.x + threadIdx.x;
    if (idx >= MR * NH) return;
    int h = idx % NH;
    int row = idx / NH;
    float v = g_zx[(size_t)row * DIP + (DIP - NH) + h] + dtb[h];
    float sp = (v > 20.f) ? v : log1pf(expf(v));
    float A = -expf(Alog[h]);
    g_dt[idx] = sp;
    g_dA[idx] = expf(sp * A);
}

// ---------------- causal depthwise conv: smem-tiled ---------------------------
#define CTS 64
#define CCS 64
__global__ void k_conv(const float* __restrict__ cw, const float* __restrict__ cb) {
    __shared__ float st[CTS + 3][CCS];
    int c0 = blockIdx.x * CCS;
    int t0 = blockIdx.y * CTS;
    int b = blockIdx.z;
    int tid = threadIdx.x;
    for (int i = tid; i < (CTS + 3) * (CCS / 4); i += 256) {
        int rr = i >> 4, cc = (i & 15) * 4;
        int t = t0 - 3 + rr;
        float4 v = make_float4(0.f, 0.f, 0.f, 0.f);
        if (t >= 0 && t < SEQ)
            v = *(const float4*)&g_zx[((size_t)(b * SEQ + t)) * DIP + DI + c0 + cc];
        *(float4*)&st[rr][cc] = v;
    }
    __syncthreads();
    int cc = (tid & 15) * 4;
    int tt = (tid >> 4) * 4;
    float4 w0 = *(const float4*)(cw + (c0 + cc) * 4);
    float4 w1 = *(const float4*)(cw + (c0 + cc + 1) * 4);
    float4 w2 = *(const float4*)(cw + (c0 + cc + 2) * 4);
    float4 w3 = *(const float4*)(cw + (c0 + cc + 3) * 4);
    float4 bias = *(const float4*)(cb + c0 + cc);
#pragma unroll
    for (int u = 0; u < 4; u++) {
        int t = t0 + tt + u;
        if (t >= SEQ) break;
        float4 xv0 = *(const float4*)&st[tt + u + 0][cc];
        float4 xv1 = *(const float4*)&st[tt + u + 1][cc];
        float4 xv2 = *(const float4*)&st[tt + u + 2][cc];
        float4 xv3 = *(const float4*)&st[tt + u + 3][cc];
        float4 acc = bias;
        acc.x += xv0.x * w0.x + xv1.x * w0.y + xv2.x * w0.z + xv3.x * w0.w;
        acc.y += xv0.y * w1.x + xv1.y * w1.y + xv2.y * w1.z + xv3.y * w1.w;
        acc.z += xv0.z * w2.x + xv1.z * w2.y + xv2.z * w2.z + xv3.z * w2.w;
        acc.w += xv0.w * w3.x + xv1.w * w3.y + xv2.w * w3.z + xv3.w * w3.w;
        float4 o = make_float4(siluf(acc.x), siluf(acc.y), siluf(acc.z), siluf(acc.w));
        *(float4*)&g_xBC[((size_t)(b * SEQ + t)) * CONV_DIM + c0 + cc] = o;
    }
}

// ---------------- chunked scan: phase A (256 thr, 4 p-blocks) ----------------
__global__ void k_scanA(const float* __restrict__ Dp) {
    __shared__ float sx[64][32];
    __shared__ float sB[64][64];
    __shared__ float sC[64][64];
    __shared__ float sdA[64];
    __shared__ float sdt[64];
    int c = blockIdx.x >> 2, pblk = blockIdx.x & 3;
    int h = blockIdx.y, b = blockIdx.z;
    int tid = threadIdx.x;
    int pl = tid >> 3, ng = tid & 7, n0 = ng * 8;
    int p = pblk * 32 + pl;
    float s[8];
#pragma unroll
    for (int j = 0; j < 8; j++) s[j] = 0.f;
    float approd = 1.f;
    float Dh = Dp[h];
    size_t baseRow = (size_t)b * SEQ;
    int xoff = h * HD + pblk * 32;
    int t0base = c * LCH;
    int tlim = min(SEQ, t0base + LCH);
    for (int t0 = t0base; t0 < tlim; t0 += 64) {
        int cnt = min(64, tlim - t0);
        for (int i = tid; i < cnt * 8; i += 256) {
            int q = i >> 3, ii = i & 7;
            ((float4*)sx[q])[ii] =
                *(const float4*)&g_xBC[(baseRow + t0 + q) * CONV_DIM + xoff + ii * 4];
        }
        for (int i = tid; i < cnt * 16; i += 256) {
            int q = i >> 4, ii = i & 15;
            ((float4*)sB[q])[ii] =
                *(const float4*)&g_xBC[(baseRow + t0 + q) * CONV_DIM + DI + ii * 4];
        }
        for (int i = tid; i < cnt * 16; i += 256) {
            int q = i >> 4, ii = i & 15;
            ((float4*)sC[q])[ii] =
                *(const float4*)&g_xBC[(baseRow + t0 + q) * CONV_DIM + DI + DSTATE + ii * 4];
        }
        for (int i = tid; i < cnt; i += 256) {
            sdA[i] = g_dA[(baseRow + t0 + i) * NH + h];
            sdt[i] = g_dt[(baseRow + t0 + i) * NH + h];
        }
        __syncthreads();
        for (int q = 0; q < cnt; q++) {
            float dA = sdA[q];
            approd *= dA;
            float xp = sx[q][pl];
            float a = sdt[q] * xp;
            float4 bb0 = *(const float4*)&sB[q][n0];
            float4 bb1 = *(const float4*)&sB[q][n0 + 4];
            float4 cc0 = *(const float4*)&sC[q][n0];
            float4 cc1 = *(const float4*)&sC[q][n0 + 4];
            float yp;
            s[0] = s[0] * dA + a * bb0.x; yp  = s[0] * cc0.x;
            s[1] = s[1] * dA + a * bb0.y; yp += s[1] * cc0.y;
            s[2] = s[2] * dA + a * bb0.z; yp += s[2] * cc0.z;
            s[3] = s[3] * dA + a * bb0.w; yp += s[3] * cc0.w;
            s[4] = s[4] * dA + a * bb1.x; yp += s[4] * cc1.x;
            s[5] = s[5] * dA + a * bb1.y; yp += s[5] * cc1.y;
            s[6] = s[6] * dA + a * bb1.z; yp += s[6] * cc1.z;
            s[7] = s[7] * dA + a * bb1.w; yp += s[7] * cc1.w;
            yp += __shfl_xor_sync(0xffffffffu, yp, 1);
            yp += __shfl_xor_sync(0xffffffffu, yp, 2);
            yp += __shfl_xor_sync(0xffffffffu, yp, 4);
            if (ng == 0)
                g_y[(baseRow + t0 + q) * DI + h * HD + p] = yp + Dh * xp;
        }
        __syncthreads();
    }
    size_t so = ((((size_t)(b * NH + h)) * TCH + c) * HD + p) * DSTATE + n0;
    *(float4*)&g_S[so]     = make_float4(s[0], s[1], s[2], s[3]);
    *(float4*)&g_S[so + 4] = make_float4(s[4], s[5], s[6], s[7]);
    if (tid == 0) g_P[(b * NH + h) * TCH + c] = approd;
}

// ---------------- chunked scan: phase B --------------------------------------
__global__ void k_scanB() {
    int idx = blockIdx.x * blockDim.x + threadIdx.x;
    if (idx >= B_SZ * NH * HD * DSTATE) return;
    int bh = idx >> 13;
    float H = 0.f;
#pragma unroll 1
    for (int c = 0; c < TCH; c++) {
        size_t o = (((size_t)bh * TCH + c) << 13) + (idx & 8191);
        g_Hb[o] = H;
        H = g_P[bh * TCH + c] * H + g_S[o];
    }
}

// ---------------- chunked scan: phase C (256 thr, 4 p-blocks) ----------------
__global__ void k_scanC() {
    __shared__ float sC[64][64];
    __shared__ float sdA[64];
    int c = (blockIdx.x >> 2) + 1, pblk = blockIdx.x & 3;
    int h = blockIdx.y, b = blockIdx.z;
    int tid = threadIdx.x;
    int pl = tid >> 3, ng = tid & 7, n0 = ng * 8;
    int p = pblk * 32 + pl;
    size_t baseRow = (size_t)b * SEQ;
    size_t ho = ((((size_t)(b * NH + h)) * TCH + c) * HD + p) * DSTATE + n0;
    float4 H0 = *(const float4*)&g_Hb[ho];
    float4 H1 = *(const float4*)&g_Hb[ho + 4];
    float ap = 1.f;
    int t0base = c * LCH;
    int tlim = min(SEQ, t0base + LCH);
    for (int t0 = t0base; t0 < tlim; t0 += 64) {
        int cnt = min(64, tlim - t0);
        for (int i = tid; i < cnt * 16; i += 256) {
            int q = i >> 4, ii = i & 15;
            ((float4*)sC[q])[ii] =
                *(const float4*)&g_xBC[(baseRow + t0 + q) * CONV_DIM + DI + DSTATE + ii * 4];
        }
        for (int i = tid; i < cnt; i += 256)
            sdA[i] = g_dA[(baseRow + t0 + i) * NH + h];
        __syncthreads();
        for (int q = 0; q < cnt; q++) {
            ap *= sdA[q];
            if (ap < 1e-37f) { ap = 0.f; break; }
            float4 cc0 = *(const float4*)&sC[q][n0];
            float4 cc1 = *(const float4*)&sC[q][n0 + 4];
            float d = H0.x * cc0.x + H0.y * cc0.y + H0.z * cc0.z + H0.w * cc0.w
                    + H1.x * cc1.x + H1.y * cc1.y + H1.z * cc1.z + H1.w * cc1.w;
            d += __shfl_xor_sync(0xffffffffu, d, 1);
            d += __shfl_xor_sync(0xffffffffu, d, 2);
            d += __shfl_xor_sync(0xffffffffu, d, 4);
            if (ng == 0)
                g_y[(baseRow + t0 + q) * DI + h * HD + p] += ap * d;
        }
        __syncthreads();
        if (ap == 0.f) break;
    }
}

// ---------------- gate + RMSNorm -> bf16 hi/lo --------------------------------
__global__ void k_gaterms(const float* __restrict__ rmsw) {
    __shared__ float red8[8];
    int row = blockIdx.x, tid = threadIdx.x;
    const float4* zr = (const float4*)(g_zx + (size_t)row * DIP);
    const float4* yr = (const float4*)(g_y + (size_t)row * DI);
    float4 z0 = zr[tid], z1 = zr[tid + 256];
    float4 y0 = yr[tid], y1 = yr[tid + 256];
    float4 g0, g1;
    g0.x = y0.x * siluf(z0.x); g0.y = y0.y * siluf(z0.y);
    g0.z = y0.z * siluf(z0.z); g0.w = y0.w * siluf(z0.w);
    g1.x = y1.x * siluf(z1.x); g1.y = y1.y * siluf(z1.y);
    g1.z = y1.z * siluf(z1.z); g1.w = y1.w * siluf(z1.w);
    float ss = g0.x * g0.x + g0.y * g0.y + g0.z * g0.z + g0.w * g0.w
             + g1.x * g1.x + g1.y * g1.y + g1.z * g1.z + g1.w * g1.w;
    float tot = blockSumN(ss, red8, 8);
    float inv = rsqrtf(tot * (1.f / DI) + 1e-5f);
    float4 w0 = ((const float4*)rmsw)[tid], w1 = ((const float4*)rmsw)[tid + 256];
    g0.x *= inv * w0.x; g0.y *= inv * w0.y; g0.z *= inv * w0.z; g0.w *= inv * w0.w;
    g1.x *= inv * w1.x; g1.y *= inv * w1.y; g1.z *= inv * w1.z; g1.w *= inv * w1.w;
    uint32_t h0, l0, h1, l1;
    size_t o = (size_t)row * (DI / 4) + tid;
    bf16split2(g0.x, g0.y, h0, l0);
    bf16split2(g0.z, g0.w, h1, l1);
    ((uint2*)g_yh)[o] = make_uint2(h0, h1);
    ((uint2*)g_yl)[o] = make_uint2(l0, l1);
    bf16split2(g1.x, g1.y, h0, l0);
    bf16split2(g1.z, g1.w, h1, l1);
    ((uint2*)g_yh)[o + 256] = make_uint2(h0, h1);
    ((uint2*)g_yl)[o + 256] = make_uint2(l0, l1);
}

// ---------------- output head: warp per pixel --------------------------------
__global__ void k_head(const float* __restrict__ w, const float* __restrict__ bias,
                       const float* __restrict__ im64, float* __restrict__ out,
                       int out_size) {
    __shared__ float sw[DM * 3];
    int tid = threadIdx.x;
    for (int i = tid; i < DM * 3; i += 256) sw[i] = w[i];
    __syncthreads();
    int lane = tid & 31, wid = tid >> 5;
    int r = blockIdx.x * 8 + wid;
    int b = r / 4096, p = r % 4096;
    const float* xr = g_x + ((size_t)(b * SEQ) + 66 + p) * DM;
    float a0 = 0.f, a1 = 0.f, a2 = 0.f;
    for (int i = lane; i < DM; i += 32) {
        float v = xr[i];
        a0 += v * sw[i * 3 + 0];
        a1 += v * sw[i * 3 + 1];
        a2 += v * sw[i * 3 + 2];
    }
#pragma unroll
    for (int o = 16; o; o >>= 1) {
        a0 += __shfl_xor_sync(0xffffffffu, a0, o);
        a1 += __shfl_xor_sync(0xffffffffu, a1, o);
        a2 += __shfl_xor_sync(0xffffffffu, a2, o);
    }
    if (lane == 0) {
        float y0 = a0 + bias[0], y1 = a1 + bias[1], y2 = a2 + bias[2];
        const float* im = im64 + (size_t)r * 3;
        float e0 = y0 - im[0], e1 = y1 - im[1], e2 = y2 - im[2];
        g_part[r] = e0 * e0 + e1 * e1 + e2 * e2;
        if (out_size >= YHAT_ELEMS) {
            out[(size_t)r * 3 + 0] = y0;
            out[(size_t)r * 3 + 1] = y1;
            out[(size_t)r * 3 + 2] = y2;
        }
    }
}

__global__ void k_loss(float* __restrict__ out, int out_size) {
    __shared__ float red8[8];
    float s = 0.f;
    for (int i = threadIdx.x; i < NPIX; i += 256) s += g_part[i];
    float tot = blockSumN(s, red8, 8);
    if (threadIdx.x == 0) {
        float loss = tot * (1.f / (float)YHAT_ELEMS);
        if (out_size <= 1) out[0] = loss;
        else if (out_size > YHAT_ELEMS) out[YHAT_ELEMS] = loss;
    }
}

// ---------------- driver -----------------------------------------------------
extern "C" void kernel_launch(void* const* d_in, const int* in_sizes, int n_in,
                              void* d_out, int out_size) {
    const float* im8        = (const float*)d_in[0];
    const float* im64       = (const float*)d_in[1];
    const float* from_rgb_w = (const float*)d_in[2];
    const float* from_rgb_b = (const float*)d_in[3];
    const float* to_rgb_w   = (const float*)d_in[4];
    const float* to_rgb_b   = (const float*)d_in[5];
    const float* s0         = (const float*)d_in[6];
    const float* s1         = (const float*)d_in[7];
    const float* posemb     = (const float*)d_in[8];
    const float* ln_w       = (const float*)d_in[9];
    const float* ln_b       = (const float*)d_in[10];
    const float* in_proj_w  = (const float*)d_in[11];
    const float* conv_w     = (const float*)d_in[12];
    const float* conv_b     = (const float*)d_in[13];
    const float* dt_bias    = (const float*)d_in[14];
    const float* A_log      = (const float*)d_in[15];
    const float* Dp         = (const float*)d_in[16];
    const float* rms_w      = (const float*)d_in[17];
    const float* out_proj_w = (const float*)d_in[18];
    float* out = (float*)d_out;

    float *p_x, *p_zx;
    cudaGetSymbolAddress((void**)&p_x, g_x);
    cudaGetSymbolAddress((void**)&p_zx, g_zx);
    __nv_bfloat16 *p_lnh, *p_lnl, *p_yh, *p_yl, *p_w1h, *p_w1l, *p_w2h, *p_w2l;
    cudaGetSymbolAddress((void**)&p_lnh, g_lnh);
    cudaGetSymbolAddress((void**)&p_lnl, g_lnl);
    cudaGetSymbolAddress((void**)&p_yh, g_yh);
    cudaGetSymbolAddress((void**)&p_yl, g_yl);
    cudaGetSymbolAddress((void**)&p_w1h, g_w1h);
    cudaGetSymbolAddress((void**)&p_w1l, g_w1l);
    cudaGetSymbolAddress((void**)&p_w2h, g_w2h);
    cudaGetSymbolAddress((void**)&p_w2l, g_w2l);

    cudaFuncSetAttribute(k_gemm_bs, cudaFuncAttributeMaxDynamicSharedMemorySize,
                         GSMEM);

    // side stream + fork/join events (created once on the first, non-captured
    // correctness call; reused during graph capture — no device allocations)
    static cudaStream_t s2 = nullptr;
    static cudaEvent_t e1 = nullptr, e2 = nullptr;
    if (!s2) {
        cudaStreamCreateWithFlags(&s2, cudaStreamNonBlocking);
        cudaEventCreateWithFlags(&e1, cudaEventDisableTiming);
        cudaEventCreateWithFlags(&e2, cudaEventDisableTiming);
    }

    {
        int n1 = NL * DIP * DM, n2 = NL * DM * DI;
        int tot = n1 / 2 + n2 / 2;
        k_wsplit2<<<(tot + 255) / 256, 256>>>(in_proj_w, out_proj_w,
                                              p_w1h, p_w1l, p_w2h, p_w2l, n1, n2);
    }
    k_embed<<<(MR * DM + 255) / 256, 256>>>(im8, from_rgb_w, from_rgb_b,
                                            s0, s1, posemb);

    const int NXBC = DIP - DI;   // 2192: xBC + dt columns
    for (int l = 0; l < NL; l++) {
        k_ln<<<MR, 256>>>(ln_w + l * DM, ln_b + l * DM);

        // GEMM1: xBC + dt columns (weight rows DI..DIP-1) -> g_zx[:, DI:]
        {
            dim3 g1((NXBC + BNT - 1) / BNT, (MR + BMT - 1) / BMT);
            k_gemm_bs<<<g1, 256, GSMEM>>>(p_lnh, p_lnl,
                                          p_w1h + (size_t)l * DIP * DM + (size_t)DI * DM,
                                          p_w1l + (size_t)l * DIP * DM + (size_t)DI * DM,
                                          p_zx, MR, NXBC, DM, DIP, DI, 0);
        }
        // fork: GEMM2 (z columns) overlaps with conv + scan chain
        cudaEventRecord(e1, 0);
        cudaStreamWaitEvent(s2, e1, 0);
        {
            dim3 g2z((DI + BNT - 1) / BNT, (MR + BMT - 1) / BMT);
            k_gemm_bs<<<g2z, 256, GSMEM, s2>>>(p_lnh, p_lnl,
                                               p_w1h + (size_t)l * DIP * DM,
                                               p_w1l + (size_t)l * DIP * DM,
                                               p_zx, MR, DI, DM, DIP, 0, 0);
        }
        cudaEventRecord(e2, s2);

        // main stream: dt, conv, scan (depend only on GEMM1)
        k_dt<<<(MR * NH + 255) / 256, 256>>>(dt_bias + l * NH, A_log + l * NH);
        dim3 gconv(CONV_DIM / CCS, (SEQ + CTS - 1) / CTS, B_SZ);
        k_conv<<<gconv, 256>>>(conv_w + l * CONV_DIM * 4, conv_b + l * CONV_DIM);

        dim3 gA(TCH * 4, NH, B_SZ);
        k_scanA<<<gA, 256>>>(Dp + l * NH);
        k_scanB<<<(B_SZ * NH * HD * DSTATE + 255) / 256, 256>>>();
        dim3 gC((TCH - 1) * 4, NH, B_SZ);
        k_scanC<<<gC, 256>>>();

        // join: gaterms needs z columns from GEMM2
        cudaStreamWaitEvent(0, e2, 0);
        k_gaterms<<<MR, 256>>>(rms_w + l * DI);

        dim3 g2((DM + BNT - 1) / BNT, (MR + BMT - 1) / BMT);
        k_gemm_bs<<<g2, 256, GSMEM>>>(p_yh, p_yl,
                                      p_w2h + (size_t)l * DM * DI,
                                      p_w2l + (size_t)l * DM * DI,
                                      p_x, MR, DM, DI, DM, 0, 1);
    }

    k_head<<<NPIX / 8, 256>>>(to_rgb_w, to_rgb_b, im64, out, out_size);
    k_loss<<<1, 256>>>(out, out_size);
}